// round 9
// baseline (speedup 1.0000x reference)
#include <cuda_runtime.h>

#define VOCAB  50000
#define EMBED  256
#define MAXLEN 512
#define UNITS  32
#define F1     16
#define BATCH  512

typedef unsigned long long ull;

// Scratch: P = emb_table @ Wx + b  [VOCAB, UNITS]  (6.4 MB, L2-resident)
__device__ float g_P[VOCAB * UNITS];

// ---- packed / MUFU helpers (sm_103a) --------------------------------------
__device__ __forceinline__ ull pack2(float lo, float hi) {
    ull d; asm("mov.b64 %0, {%1, %2};" : "=l"(d) : "f"(lo), "f"(hi)); return d;
}
__device__ __forceinline__ ull fma2(ull a, ull b, ull c) {
    ull d; asm("fma.rn.f32x2 %0, %1, %2, %3;" : "=l"(d) : "l"(a), "l"(b), "l"(c)); return d;
}
__device__ __forceinline__ ull add2(ull a, ull b) {
    ull d; asm("add.rn.f32x2 %0, %1, %2;" : "=l"(d) : "l"(a), "l"(b)); return d;
}
__device__ __forceinline__ void unpack2(ull s, float& lo, float& hi) {
    asm("mov.b64 {%0, %1}, %2;" : "=f"(lo), "=f"(hi) : "l"(s));
}
__device__ __forceinline__ float ex2f(float x) {
    float y; asm("ex2.approx.f32 %0, %1;" : "=f"(y) : "f"(x)); return y;
}
__device__ __forceinline__ float rcpf(float x) {
    float y; asm("rcp.approx.f32 %0, %1;" : "=f"(y) : "f"(x)); return y;
}
__device__ __forceinline__ float tanhf_mufu(float x) {
    float y; asm("tanh.approx.f32 %0, %1;" : "=f"(y) : "f"(x)); return y;
}

// ---------------------------------------------------------------------------
// Kernel 1: P[v][j] = sum_e emb[v][e]*Wx[e][j] + b[j]
// 128 threads: 2 cols (p, p+16) x 8 rows per thread. Same 64-row tile
// (2 blocks/SM for stage/compute overlap), LDS per fma2 drops 0.5 -> 0.375.
// Transposed weights stride 258 (conflict-free), LDS.64 weight loads.
// ---------------------------------------------------------------------------
#define PK_ROWS    64
#define PK_THREADS 128
#define WXT_STRIDE 258
#define PK_SMEM    ((UNITS*WXT_STRIDE + PK_ROWS*EMBED) * 4)   // ~33KB + 64KB

__global__ void __launch_bounds__(PK_THREADS, 1)
compute_P_kernel(const float* __restrict__ emb, const float* __restrict__ Wx,
                 const float* __restrict__ bias)
{
    extern __shared__ float smem[];
    float* wxT   = smem;                         // [UNITS][WXT_STRIDE]
    float* emb_s = smem + UNITS * WXT_STRIDE;    // [PK_ROWS][EMBED]

    const int tid = threadIdx.x;
    const int v0  = blockIdx.x * PK_ROWS;

    #pragma unroll
    for (int i = tid; i < EMBED * UNITS; i += PK_THREADS) {
        int j = i & 31, e = i >> 5;
        wxT[j * WXT_STRIDE + e] = Wx[i];
    }

    {
        const float4* e4  = reinterpret_cast<const float4*>(emb);
        float4*       es4 = reinterpret_cast<float4*>(emb_s);
        const int base4 = v0 * (EMBED / 4);
        const int max4  = VOCAB * (EMBED / 4);
        #pragma unroll
        for (int i = tid; i < PK_ROWS * (EMBED / 4); i += PK_THREADS) {
            int gi = base4 + i;
            es4[i] = (gi < max4) ? e4[gi] : make_float4(0.f, 0.f, 0.f, 0.f);
        }
    }
    __syncthreads();

    const int p  = tid & 15;          // columns p and p+16
    const int rg = tid >> 4;          // rows rg*8 .. rg*8+7

    const ull* wp = reinterpret_cast<const ull*>(wxT + p * WXT_STRIDE);
    const ull* wq = reinterpret_cast<const ull*>(wxT + (p + 16) * WXT_STRIDE);
    const float* er = emb_s + rg * 8 * EMBED;

    ull accP[8] = {0,0,0,0,0,0,0,0}, accQ[8] = {0,0,0,0,0,0,0,0};

    #pragma unroll 4
    for (int e = 0; e < EMBED; e += 4) {
        ull wp0 = wp[(e >> 1)];
        ull wp1 = wp[(e >> 1) + 1];
        ull wq0 = wq[(e >> 1)];
        ull wq1 = wq[(e >> 1) + 1];
        #pragma unroll
        for (int r = 0; r < 8; r++) {
            ulonglong2 ev = *reinterpret_cast<const ulonglong2*>(er + r * EMBED + e);
            accP[r] = fma2(ev.x, wp0, accP[r]);
            accP[r] = fma2(ev.y, wp1, accP[r]);
            accQ[r] = fma2(ev.x, wq0, accQ[r]);
            accQ[r] = fma2(ev.y, wq1, accQ[r]);
        }
    }

    const float bp = bias[p], bq = bias[p + 16];
    #pragma unroll
    for (int r = 0; r < 8; r++) {
        int v = v0 + rg * 8 + r;
        if (v < VOCAB) {
            float lo, hi;
            unpack2(accP[r], lo, hi);
            g_P[v * UNITS + p] = lo + hi + bp;
            unpack2(accQ[r], lo, hi);
            g_P[v * UNITS + p + 16] = lo + hi + bq;
        }
    }
}

// ---------------------------------------------------------------------------
// Kernel 2: RNN recurrence + head. One warp per batch row, lane = unit.
//   h' = tanh.approx( P[tok] + sum_k h_k * Wh[k][lane] )
// Round-8 base (best: smem exchange + syncwarp, token pipelining, mufu tanh)
// with an issue diet:
//  - STS + syncwarp FIRST in the body (LDG/token/pointer ops fill the sync
//    drain window instead of delaying the loop-carried STS).
//  - 4 fma2 chains of depth 4 + 2-level add2 tree (-4 add2 instrs).
//  - unroll 8 (halved loop overhead; body still fits L0 I$).
// ---------------------------------------------------------------------------
#define R_WARPS   4
#define R_THREADS 128
#define TOKPAD    (MAXLEN + 8)

__global__ void __launch_bounds__(R_THREADS, 1)
rnn_kernel(const int*   __restrict__ tokens,
           const float* __restrict__ W1,
           const float* __restrict__ b1,
           const float* __restrict__ W2,
           const float* __restrict__ b2,
           const float* __restrict__ Wh,
           float*       __restrict__ out)
{
    __shared__ __align__(16) float h_s[R_WARPS][2][UNITS];
    __shared__ __align__(16) int tok_s[R_WARPS][TOKPAD];

    const unsigned FULL = 0xffffffffu;
    const int tid  = threadIdx.x;
    const int lane = tid & 31;
    const int wid  = tid >> 5;
    const int b    = blockIdx.x * R_WARPS + wid;

    // stage this block's 4 token rows (int4), pad 8 entries per row with 0
    {
        const int4* src = reinterpret_cast<const int4*>(tokens + blockIdx.x * R_WARPS * MAXLEN);
        #pragma unroll
        for (int i = tid; i < R_WARPS * (MAXLEN / 4); i += R_THREADS) {
            int row = i >> 7;
            int col = i & 127;
            reinterpret_cast<int4*>(&tok_s[row][0])[col] = src[i];
        }
        if (tid < R_WARPS * 8)
            tok_s[tid >> 3][MAXLEN + (tid & 7)] = 0;
    }
    __syncthreads();

    // packed weights: whp[p] = {Wh[2p][lane], Wh[2p+1][lane]}
    ull whp[UNITS / 2];
    #pragma unroll
    for (int p = 0; p < UNITS / 2; p++)
        whp[p] = pack2(Wh[(2 * p) * UNITS + lane], Wh[(2 * p + 1) * UNITS + lane]);

    const int* trow = tok_s[wid];

    // prefetch ring: P rows for steps t..t+2 plus the TOKEN for t+3
    float pv0 = g_P[trow[0] * UNITS + lane];
    float pv1 = g_P[trow[1] * UNITS + lane];
    float pv2 = g_P[trow[2] * UNITS + lane];
    int   tokn = trow[3];

    float h = 0.f;

    #pragma unroll 8
    for (int t = 0; t < MAXLEN; t++) {
        // exchange h FIRST: the loop-carried STS goes out immediately after
        // tanh; prefetches below fill the syncwarp drain window.
        float* buf = h_s[wid][t & 1];
        buf[lane] = h;
        __syncwarp();

        // P row for t+3 via register token (no fresh-LDS stall); token t+4
        float pv3 = g_P[tokn * UNITS + lane];
        int toknext = trow[t + 4];

        const ulonglong2* hb = reinterpret_cast<const ulonglong2*>(buf);
        ulonglong2 v0 = hb[0], v1 = hb[1], v2 = hb[2], v3 = hb[3];
        ulonglong2 v4 = hb[4], v5 = hb[5], v6 = hb[6], v7 = hb[7];

        // 4 chains of depth 4
        ull A0 = fma2(v0.x, whp[0],  pack2(pv0, 0.f));
        ull A1 = fma2(v0.y, whp[1],  0ULL);
        ull A2 = fma2(v1.x, whp[2],  0ULL);
        ull A3 = fma2(v1.y, whp[3],  0ULL);
        A0 = fma2(v2.x, whp[4],  A0);
        A1 = fma2(v2.y, whp[5],  A1);
        A2 = fma2(v3.x, whp[6],  A2);
        A3 = fma2(v3.y, whp[7],  A3);
        A0 = fma2(v4.x, whp[8],  A0);
        A1 = fma2(v4.y, whp[9],  A1);
        A2 = fma2(v5.x, whp[10], A2);
        A3 = fma2(v5.y, whp[11], A3);
        A0 = fma2(v6.x, whp[12], A0);
        A1 = fma2(v6.y, whp[13], A1);
        A2 = fma2(v7.x, whp[14], A2);
        A3 = fma2(v7.y, whp[15], A3);

        ull D = add2(add2(A0, A1), add2(A2, A3));
        float zlo, zhi; unpack2(D, zlo, zhi);

        h = tanhf_mufu(zlo + zhi);

        pv0 = pv1; pv1 = pv2; pv2 = pv3; tokn = toknext;
    }

    // ---- head: z = (h @ W1 + b1) @ W2 + b2 ; out = sigmoid(z) ----
    float w1c[UNITS];
    #pragma unroll
    for (int k = 0; k < UNITS; k++)
        w1c[k] = (lane < F1) ? W1[k * F1 + lane] : 0.f;

    float y = (lane < F1) ? b1[lane] : 0.f;
    #pragma unroll
    for (int k = 0; k < UNITS; k++)
        y = fmaf(__shfl_sync(FULL, h, k), w1c[k], y);

    float w2v = (lane < F1) ? W2[lane] : 0.f;
    float contrib = y * w2v;
    #pragma unroll
    for (int off = 16; off > 0; off >>= 1)
        contrib += __shfl_xor_sync(FULL, contrib, off);

    if (lane == 0) {
        float zz = contrib + b2[0];
        out[b] = rcpf(1.f + ex2f(-1.4426950408889634f * zz));
    }
}

// ---------------------------------------------------------------------------
extern "C" void kernel_launch(void* const* d_in, const int* in_sizes, int n_in,
                              void* d_out, int out_size)
{
    const int*   tokens = (const int*)  d_in[0];
    const float* emb    = (const float*)d_in[1];
    const float* Wx     = (const float*)d_in[2];
    const float* Wh     = (const float*)d_in[3];
    const float* bias   = (const float*)d_in[4];
    const float* W1     = (const float*)d_in[5];
    const float* b1     = (const float*)d_in[6];
    const float* W2     = (const float*)d_in[7];
    const float* b2     = (const float*)d_in[8];
    float* out = (float*)d_out;

    cudaFuncSetAttribute((const void*)compute_P_kernel,
                         cudaFuncAttributeMaxDynamicSharedMemorySize, PK_SMEM);

    compute_P_kernel<<<(VOCAB + PK_ROWS - 1) / PK_ROWS, PK_THREADS, PK_SMEM>>>(emb, Wx, bias);
    rnn_kernel<<<BATCH / R_WARPS, R_THREADS>>>(tokens, W1, b1, W2, b2, Wh, out);
}

// round 10
// speedup vs baseline: 1.0825x; 1.0825x over previous
#include <cuda_runtime.h>

#define VOCAB  50000
#define EMBED  256
#define MAXLEN 512
#define UNITS  32
#define F1     16
#define BATCH  512

typedef unsigned long long ull;

// Scratch: P = emb_table @ Wx + b  [VOCAB, UNITS]  (6.4 MB, L2-resident)
__device__ float g_P[VOCAB * UNITS];

// ---- packed / MUFU helpers (sm_103a) --------------------------------------
__device__ __forceinline__ ull pack2(float lo, float hi) {
    ull d; asm("mov.b64 %0, {%1, %2};" : "=l"(d) : "f"(lo), "f"(hi)); return d;
}
__device__ __forceinline__ ull fma2(ull a, ull b, ull c) {
    ull d; asm("fma.rn.f32x2 %0, %1, %2, %3;" : "=l"(d) : "l"(a), "l"(b), "l"(c)); return d;
}
__device__ __forceinline__ ull add2(ull a, ull b) {
    ull d; asm("add.rn.f32x2 %0, %1, %2;" : "=l"(d) : "l"(a), "l"(b)); return d;
}
__device__ __forceinline__ void unpack2(ull s, float& lo, float& hi) {
    asm("mov.b64 {%0, %1}, %2;" : "=f"(lo), "=f"(hi) : "l"(s));
}
__device__ __forceinline__ float ex2f(float x) {
    float y; asm("ex2.approx.f32 %0, %1;" : "=f"(y) : "f"(x)); return y;
}
__device__ __forceinline__ float rcpf(float x) {
    float y; asm("rcp.approx.f32 %0, %1;" : "=f"(y) : "f"(x)); return y;
}
__device__ __forceinline__ float tanhf_mufu(float x) {
    float y; asm("tanh.approx.f32 %0, %1;" : "=f"(y) : "f"(x)); return y;
}

// ---------------------------------------------------------------------------
// Kernel 1: P[v][j] = sum_e emb[v][e]*Wx[e][j] + b[j]
// ROUND-9 VERSION (measured 16.2us — best). 128 threads: 2 cols x 8 rows
// per thread; transposed weights stride 258 (conflict-free); LDS.64 weight
// loads (rows 8B-aligned only).
// ---------------------------------------------------------------------------
#define PK_ROWS    64
#define PK_THREADS 128
#define WXT_STRIDE 258
#define PK_SMEM    ((UNITS*WXT_STRIDE + PK_ROWS*EMBED) * 4)   // ~33KB + 64KB

__global__ void __launch_bounds__(PK_THREADS, 1)
compute_P_kernel(const float* __restrict__ emb, const float* __restrict__ Wx,
                 const float* __restrict__ bias)
{
    extern __shared__ float smem[];
    float* wxT   = smem;                         // [UNITS][WXT_STRIDE]
    float* emb_s = smem + UNITS * WXT_STRIDE;    // [PK_ROWS][EMBED]

    const int tid = threadIdx.x;
    const int v0  = blockIdx.x * PK_ROWS;

    #pragma unroll
    for (int i = tid; i < EMBED * UNITS; i += PK_THREADS) {
        int j = i & 31, e = i >> 5;
        wxT[j * WXT_STRIDE + e] = Wx[i];
    }

    {
        const float4* e4  = reinterpret_cast<const float4*>(emb);
        float4*       es4 = reinterpret_cast<float4*>(emb_s);
        const int base4 = v0 * (EMBED / 4);
        const int max4  = VOCAB * (EMBED / 4);
        #pragma unroll
        for (int i = tid; i < PK_ROWS * (EMBED / 4); i += PK_THREADS) {
            int gi = base4 + i;
            es4[i] = (gi < max4) ? e4[gi] : make_float4(0.f, 0.f, 0.f, 0.f);
        }
    }
    __syncthreads();

    const int p  = tid & 15;          // columns p and p+16
    const int rg = tid >> 4;          // rows rg*8 .. rg*8+7

    const ull* wp = reinterpret_cast<const ull*>(wxT + p * WXT_STRIDE);
    const ull* wq = reinterpret_cast<const ull*>(wxT + (p + 16) * WXT_STRIDE);
    const float* er = emb_s + rg * 8 * EMBED;

    ull accP[8] = {0,0,0,0,0,0,0,0}, accQ[8] = {0,0,0,0,0,0,0,0};

    #pragma unroll 4
    for (int e = 0; e < EMBED; e += 4) {
        ull wp0 = wp[(e >> 1)];
        ull wp1 = wp[(e >> 1) + 1];
        ull wq0 = wq[(e >> 1)];
        ull wq1 = wq[(e >> 1) + 1];
        #pragma unroll
        for (int r = 0; r < 8; r++) {
            ulonglong2 ev = *reinterpret_cast<const ulonglong2*>(er + r * EMBED + e);
            accP[r] = fma2(ev.x, wp0, accP[r]);
            accP[r] = fma2(ev.y, wp1, accP[r]);
            accQ[r] = fma2(ev.x, wq0, accQ[r]);
            accQ[r] = fma2(ev.y, wq1, accQ[r]);
        }
    }

    const float bp = bias[p], bq = bias[p + 16];
    #pragma unroll
    for (int r = 0; r < 8; r++) {
        int v = v0 + rg * 8 + r;
        if (v < VOCAB) {
            float lo, hi;
            unpack2(accP[r], lo, hi);
            g_P[v * UNITS + p] = lo + hi + bp;
            unpack2(accQ[r], lo, hi);
            g_P[v * UNITS + p + 16] = lo + hi + bq;
        }
    }
}

// ---------------------------------------------------------------------------
// Kernel 2: RNN recurrence + head. ROUND-8 VERSION VERBATIM (measured
// 62.7us — best). One warp per batch row, lane = unit.
//   h' = tanh.approx( P[tok] + sum_k h_k * Wh[k][lane] )
// Order matters (round 9 proved it): LDG + token-LDS issued BEFORE the
// STS+syncwarp so they drain during the sync window; 8 fma2 chains of
// depth 2; unroll 4 (body well inside L0 I$).
// ---------------------------------------------------------------------------
#define R_WARPS   4
#define R_THREADS 128
#define TOKPAD    (MAXLEN + 8)

__global__ void __launch_bounds__(R_THREADS, 1)
rnn_kernel(const int*   __restrict__ tokens,
           const float* __restrict__ W1,
           const float* __restrict__ b1,
           const float* __restrict__ W2,
           const float* __restrict__ b2,
           const float* __restrict__ Wh,
           float*       __restrict__ out)
{
    __shared__ __align__(16) float h_s[R_WARPS][2][UNITS];
    __shared__ __align__(16) int tok_s[R_WARPS][TOKPAD];

    const unsigned FULL = 0xffffffffu;
    const int tid  = threadIdx.x;
    const int lane = tid & 31;
    const int wid  = tid >> 5;
    const int b    = blockIdx.x * R_WARPS + wid;

    // stage this block's 4 token rows (int4), pad 8 entries per row with 0
    {
        const int4* src = reinterpret_cast<const int4*>(tokens + blockIdx.x * R_WARPS * MAXLEN);
        #pragma unroll
        for (int i = tid; i < R_WARPS * (MAXLEN / 4); i += R_THREADS) {
            int row = i >> 7;
            int col = i & 127;
            reinterpret_cast<int4*>(&tok_s[row][0])[col] = src[i];
        }
        if (tid < R_WARPS * 8)
            tok_s[tid >> 3][MAXLEN + (tid & 7)] = 0;
    }
    __syncthreads();

    // packed weights: whp[p] = {Wh[2p][lane], Wh[2p+1][lane]}
    ull whp[UNITS / 2];
    #pragma unroll
    for (int p = 0; p < UNITS / 2; p++)
        whp[p] = pack2(Wh[(2 * p) * UNITS + lane], Wh[(2 * p + 1) * UNITS + lane]);

    const int* trow = tok_s[wid];

    // prefetch ring: P rows for steps t, t+1, t+2 plus the TOKEN for t+3
    float pv0 = g_P[trow[0] * UNITS + lane];
    float pv1 = g_P[trow[1] * UNITS + lane];
    float pv2 = g_P[trow[2] * UNITS + lane];
    int   tokn = trow[3];

    float h = 0.f;

    #pragma unroll 4
    for (int t = 0; t < MAXLEN; t++) {
        // LDG uses a register token (loaded last iteration) -> no LDS stall
        float pv3 = g_P[tokn * UNITS + lane];
        // token for step t+4, consumed NEXT iteration (padded: no bounds SEL)
        int toknext = trow[t + 4];

        // exchange h across the warp (double-buffered, one syncwarp)
        float* buf = h_s[wid][t & 1];
        buf[lane] = h;
        __syncwarp();
        const ulonglong2* hb = reinterpret_cast<const ulonglong2*>(buf);
        ulonglong2 v0 = hb[0], v1 = hb[1], v2 = hb[2], v3 = hb[3];
        ulonglong2 v4 = hb[4], v5 = hb[5], v6 = hb[6], v7 = hb[7];

        // 8 chains of depth 2
        ull A0 = fma2(v0.x, whp[0],  pack2(pv0, 0.f));
        ull A1 = fma2(v0.y, whp[1],  0ULL);
        ull A2 = fma2(v1.x, whp[2],  0ULL);
        ull A3 = fma2(v1.y, whp[3],  0ULL);
        ull A4 = fma2(v2.x, whp[4],  0ULL);
        ull A5 = fma2(v2.y, whp[5],  0ULL);
        ull A6 = fma2(v3.x, whp[6],  0ULL);
        ull A7 = fma2(v3.y, whp[7],  0ULL);
        A0 = fma2(v4.x, whp[8],  A0);
        A1 = fma2(v4.y, whp[9],  A1);
        A2 = fma2(v5.x, whp[10], A2);
        A3 = fma2(v5.y, whp[11], A3);
        A4 = fma2(v6.x, whp[12], A4);
        A5 = fma2(v6.y, whp[13], A5);
        A6 = fma2(v7.x, whp[14], A6);
        A7 = fma2(v7.y, whp[15], A7);

        ull B0 = add2(A0, A1), B1 = add2(A2, A3);
        ull B2 = add2(A4, A5), B3 = add2(A6, A7);
        ull D  = add2(add2(B0, B1), add2(B2, B3));
        float zlo, zhi; unpack2(D, zlo, zhi);

        h = tanhf_mufu(zlo + zhi);

        pv0 = pv1; pv1 = pv2; pv2 = pv3; tokn = toknext;
    }

    // ---- head: z = (h @ W1 + b1) @ W2 + b2 ; out = sigmoid(z) ----
    float w1c[UNITS];
    #pragma unroll
    for (int k = 0; k < UNITS; k++)
        w1c[k] = (lane < F1) ? W1[k * F1 + lane] : 0.f;

    float y = (lane < F1) ? b1[lane] : 0.f;
    #pragma unroll
    for (int k = 0; k < UNITS; k++)
        y = fmaf(__shfl_sync(FULL, h, k), w1c[k], y);

    float w2v = (lane < F1) ? W2[lane] : 0.f;
    float contrib = y * w2v;
    #pragma unroll
    for (int off = 16; off > 0; off >>= 1)
        contrib += __shfl_xor_sync(FULL, contrib, off);

    if (lane == 0) {
        float zz = contrib + b2[0];
        out[b] = rcpf(1.f + ex2f(-1.4426950408889634f * zz));
    }
}

// ---------------------------------------------------------------------------
extern "C" void kernel_launch(void* const* d_in, const int* in_sizes, int n_in,
                              void* d_out, int out_size)
{
    const int*   tokens = (const int*)  d_in[0];
    const float* emb    = (const float*)d_in[1];
    const float* Wx     = (const float*)d_in[2];
    const float* Wh     = (const float*)d_in[3];
    const float* bias   = (const float*)d_in[4];
    const float* W1     = (const float*)d_in[5];
    const float* b1     = (const float*)d_in[6];
    const float* W2     = (const float*)d_in[7];
    const float* b2     = (const float*)d_in[8];
    float* out = (float*)d_out;

    cudaFuncSetAttribute((const void*)compute_P_kernel,
                         cudaFuncAttributeMaxDynamicSharedMemorySize, PK_SMEM);

    compute_P_kernel<<<(VOCAB + PK_ROWS - 1) / PK_ROWS, PK_THREADS, PK_SMEM>>>(emb, Wx, bias);
    rnn_kernel<<<BATCH / R_WARPS, R_THREADS>>>(tokens, W1, b1, W2, b2, Wh, out);
}